// round 5
// baseline (speedup 1.0000x reference)
#include <cuda_runtime.h>
#include <math.h>

#define NROWS 8192
#define NCOLS 8192
#define RB 32
#define CB 32
#define HID 100
#define DIO (RB * CB)                  // 1024
#define ROWS_PER_CTA 128
#define THREADS_RED 128
#define STRIP_COLS (THREADS_RED * 4)   // 512 columns per CTA strip
#define ST_V4 (NCOLS / 4)              // float4 row stride
#define MAXRUNS 33

// Device-global scratch (no allocations allowed). Accumulators (g_blk, g_h1)
// start zero and are re-zeroed by downstream kernels after being consumed.
// g_h2/g_rcum/g_ccum are fully overwritten each replay.
__device__ float g_blk[DIO];
__device__ float g_h1[HID];
__device__ float g_h2[HID];
__device__ int   g_rcum[RB + 1];
__device__ int   g_ccum[CB + 1];

__device__ __forceinline__ int lb_count_less(const int* __restrict__ a,
                                             int n, int key) {
    int lo = 0, hi = n;
    while (lo < hi) {
        int mid = (lo + hi) >> 1;
        if (__ldg(&a[mid]) < key) lo = mid + 1; else hi = mid;
    }
    return lo;
}

// ---------------------------------------------------------------------------
// Kernel 1: segmented block-sum reduce of X (HBM-bound, ~99.9% of bytes).
// Grid (16, 64) = 1024 CTAs x 128 thr. Run-based branch-free hot loop with
// 16 front-batched float4 streaming loads (MLP ~ 16) and two independent
// accumulator quads (halved dependent-FADD chain).
// CTA (0,0) additionally computes the cumsums (independent of X).
// ---------------------------------------------------------------------------
__global__ __launch_bounds__(THREADS_RED)
void mar_reduce_kernel(const float* __restrict__ X,
                       const int* __restrict__ row_ids,
                       const int* __restrict__ col_ids,
                       float* __restrict__ out) {
    __shared__ float s_blk[DIO];
    __shared__ unsigned char s_rseg[ROWS_PER_CTA];
    __shared__ short s_run_start[MAXRUNS + 1];
    __shared__ unsigned char s_run_seg[MAXRUNS];
    __shared__ int s_nrun;

    const int tid = threadIdx.x;
    const int r0 = blockIdx.y * ROWS_PER_CTA;
    const int c0 = blockIdx.x * STRIP_COLS + tid * 4;

    for (int i = tid; i < DIO; i += THREADS_RED) s_blk[i] = 0.0f;
    if (tid < ROWS_PER_CTA)
        s_rseg[tid] = (unsigned char)row_ids[r0 + tid];

    const int cs0 = col_ids[c0 + 0];
    const int cs1 = col_ids[c0 + 1];
    const int cs2 = col_ids[c0 + 2];
    const int cs3 = col_ids[c0 + 3];
    __syncthreads();

    // Build run list (sorted ids -> typically 1-2 runs per 128-row chunk).
    if (tid == 0) {
        int n = 0, prev = -1;
        for (int r = 0; r < ROWS_PER_CTA; r++) {
            int s = s_rseg[r];
            if (s != prev) {
                s_run_start[n] = (short)r;
                s_run_seg[n] = (unsigned char)s;
                n++; prev = s;
            }
        }
        s_run_start[n] = ROWS_PER_CTA;
        s_nrun = n;
    }
    __syncthreads();

    const float4* __restrict__ p = (const float4*)(X + (size_t)r0 * NCOLS + c0);
    const int nrun = s_nrun;

    for (int run = 0; run < nrun; run++) {
        const int rs = s_run_start[run];
        const int re = s_run_start[run + 1];
        const int seg = s_run_seg[run];
        const float4* __restrict__ q = p + (size_t)rs * ST_V4;
        const int n = re - rs;

        float a0 = 0.f, a1 = 0.f, a2 = 0.f, a3 = 0.f;
        float b0 = 0.f, b1 = 0.f, b2 = 0.f, b3 = 0.f;
        int r = 0;
        // 16 independent streaming loads batched up front, 2 accum quads.
        for (; r + 16 <= n; r += 16) {
            float4 v0 = __ldcs(&q[(size_t)(r + 0) * ST_V4]);
            float4 v1 = __ldcs(&q[(size_t)(r + 1) * ST_V4]);
            float4 v2 = __ldcs(&q[(size_t)(r + 2) * ST_V4]);
            float4 v3 = __ldcs(&q[(size_t)(r + 3) * ST_V4]);
            float4 v4 = __ldcs(&q[(size_t)(r + 4) * ST_V4]);
            float4 v5 = __ldcs(&q[(size_t)(r + 5) * ST_V4]);
            float4 v6 = __ldcs(&q[(size_t)(r + 6) * ST_V4]);
            float4 v7 = __ldcs(&q[(size_t)(r + 7) * ST_V4]);
            float4 v8 = __ldcs(&q[(size_t)(r + 8) * ST_V4]);
            float4 v9 = __ldcs(&q[(size_t)(r + 9) * ST_V4]);
            float4 va = __ldcs(&q[(size_t)(r + 10) * ST_V4]);
            float4 vb = __ldcs(&q[(size_t)(r + 11) * ST_V4]);
            float4 vc = __ldcs(&q[(size_t)(r + 12) * ST_V4]);
            float4 vd = __ldcs(&q[(size_t)(r + 13) * ST_V4]);
            float4 ve = __ldcs(&q[(size_t)(r + 14) * ST_V4]);
            float4 vf = __ldcs(&q[(size_t)(r + 15) * ST_V4]);
            a0 += v0.x; a1 += v0.y; a2 += v0.z; a3 += v0.w;
            b0 += v1.x; b1 += v1.y; b2 += v1.z; b3 += v1.w;
            a0 += v2.x; a1 += v2.y; a2 += v2.z; a3 += v2.w;
            b0 += v3.x; b1 += v3.y; b2 += v3.z; b3 += v3.w;
            a0 += v4.x; a1 += v4.y; a2 += v4.z; a3 += v4.w;
            b0 += v5.x; b1 += v5.y; b2 += v5.z; b3 += v5.w;
            a0 += v6.x; a1 += v6.y; a2 += v6.z; a3 += v6.w;
            b0 += v7.x; b1 += v7.y; b2 += v7.z; b3 += v7.w;
            a0 += v8.x; a1 += v8.y; a2 += v8.z; a3 += v8.w;
            b0 += v9.x; b1 += v9.y; b2 += v9.z; b3 += v9.w;
            a0 += va.x; a1 += va.y; a2 += va.z; a3 += va.w;
            b0 += vb.x; b1 += vb.y; b2 += vb.z; b3 += vb.w;
            a0 += vc.x; a1 += vc.y; a2 += vc.z; a3 += vc.w;
            b0 += vd.x; b1 += vd.y; b2 += vd.z; b3 += vd.w;
            a0 += ve.x; a1 += ve.y; a2 += ve.z; a3 += ve.w;
            b0 += vf.x; b1 += vf.y; b2 += vf.z; b3 += vf.w;
        }
        for (; r + 4 <= n; r += 4) {
            float4 v0 = __ldcs(&q[(size_t)(r + 0) * ST_V4]);
            float4 v1 = __ldcs(&q[(size_t)(r + 1) * ST_V4]);
            float4 v2 = __ldcs(&q[(size_t)(r + 2) * ST_V4]);
            float4 v3 = __ldcs(&q[(size_t)(r + 3) * ST_V4]);
            a0 += v0.x; a1 += v0.y; a2 += v0.z; a3 += v0.w;
            b0 += v1.x; b1 += v1.y; b2 += v1.z; b3 += v1.w;
            a0 += v2.x; a1 += v2.y; a2 += v2.z; a3 += v2.w;
            b0 += v3.x; b1 += v3.y; b2 += v3.z; b3 += v3.w;
        }
        for (; r < n; r++) {
            float4 v = __ldcs(&q[(size_t)r * ST_V4]);
            a0 += v.x; a1 += v.y; a2 += v.z; a3 += v.w;
        }
        const int base = seg * CB;
        atomicAdd(&s_blk[base + cs0], a0 + b0);
        atomicAdd(&s_blk[base + cs1], a1 + b1);
        atomicAdd(&s_blk[base + cs2], a2 + b2);
        atomicAdd(&s_blk[base + cs3], a3 + b3);
    }
    __syncthreads();

    for (int i = tid; i < DIO; i += THREADS_RED) {
        float v = s_blk[i];
        if (v != 0.0f) atomicAdd(&g_blk[i], v);
    }

    // Side task (one CTA): cumsums via lower_bound on sorted ids.
    if (blockIdx.x == 0 && blockIdx.y == 0) {
        if (tid <= RB) {
            int v = lb_count_less(row_ids, NROWS, tid);
            g_rcum[tid] = v;
            out[DIO + tid] = (float)v;
        } else if (tid < 2 * (RB + 1)) {
            int t = tid - (RB + 1);
            int v = lb_count_less(col_ids, NCOLS, t);
            g_ccum[t] = v;
            out[DIO + (RB + 1) + t] = (float)v;
        }
    }
}

// ---------------------------------------------------------------------------
// Kernel 2: Layer 1 partials, grid 16 x 256. CTA c handles input rows
// [c*64, (c+1)*64); two thread-halves of 32 rows each; partial dot products
// atomically accumulated into g_h1 (init 0; bias added in kernel 3).
// ---------------------------------------------------------------------------
__global__ __launch_bounds__(256)
void mar_l1_kernel(const float* __restrict__ W1) {
    __shared__ float s_x[64];
    const int tid = threadIdx.x;
    const int i0 = blockIdx.x * 64;

    if (tid < 64) {
        int i = i0 + tid;
        int ri = i >> 5, ci = i & 31;
        float rc = (float)(g_rcum[ri + 1] - g_rcum[ri]);
        float cc = (float)(g_ccum[ci + 1] - g_ccum[ci]);
        s_x[tid] = g_blk[i] / fmaxf(rc * cc, 1.0f);
    }
    __syncthreads();

    const int half = tid >> 7;        // 0 or 1: 32 input rows each
    const int k = tid & 127;
    if (k < HID) {
        float s = 0.0f;
        const float* __restrict__ w = W1 + (size_t)(i0 + half * 32) * HID + k;
        const float* __restrict__ xs = s_x + half * 32;
#pragma unroll 32
        for (int i = 0; i < 32; i++)
            s += xs[i] * __ldg(&w[(size_t)i * HID]);
        atomicAdd(&g_h1[k], s);
    }
}

// ---------------------------------------------------------------------------
// Kernel 3: relu(h1 + b1) -> Layer 2 (100x100) -> g_h2.
// Also self-cleans the accumulators (g_h1, g_blk) for the next replay.
// ---------------------------------------------------------------------------
__global__ __launch_bounds__(128)
void mar_l2_kernel(const float* __restrict__ b1,
                   const float* __restrict__ W2,
                   const float* __restrict__ b2) {
    __shared__ float s_h1[HID];
    const int tid = threadIdx.x;

    if (tid < HID) {
        s_h1[tid] = fmaxf(g_h1[tid] + b1[tid], 0.0f);
        g_h1[tid] = 0.0f;                 // consumed -> clean for next replay
    }
    for (int i = tid; i < DIO; i += 128)  // g_blk consumed by kernel 2
        g_blk[i] = 0.0f;
    __syncthreads();

    if (tid < HID) {
        float s = b2[tid];
        const float* __restrict__ w = W2 + tid;
#pragma unroll 20
        for (int i = 0; i < HID; i++)
            s += s_h1[i] * __ldg(&w[(size_t)i * HID]);
        g_h2[tid] = fmaxf(s, 0.0f);       // full overwrite, no cleaning needed
    }
}

// ---------------------------------------------------------------------------
// Kernel 4: Layer 3 + sigmoid, grid 8 x 512 (split-K: 4 threads per output
// column, 25 i-rows each, shared combine). 4x the in-flight loads of the
// previous 8x128 version.
// ---------------------------------------------------------------------------
__global__ __launch_bounds__(512)
void mar_l3_kernel(const float* __restrict__ W3,
                   const float* __restrict__ b3,
                   float* __restrict__ out) {
    __shared__ float s_h2[HID];
    __shared__ float s_part[3][128];
    const int tid = threadIdx.x;
    if (tid < HID) s_h2[tid] = g_h2[tid];
    __syncthreads();

    const int lane = tid & 127;
    const int part = tid >> 7;              // 0..3
    const int j = blockIdx.x * 128 + lane;
    const int ibeg = part * 25;

    float s = 0.0f;
    const float* __restrict__ w = W3 + (size_t)ibeg * DIO + j;
#pragma unroll 25
    for (int i = 0; i < 25; i++)
        s += s_h2[ibeg + i] * __ldg(&w[(size_t)i * DIO]);

    if (part) s_part[part - 1][lane] = s;
    __syncthreads();
    if (part == 0) {
        s += b3[j] + s_part[0][lane] + s_part[1][lane] + s_part[2][lane];
        out[j] = 1.0f / (1.0f + expf(-s));
    }
}

// ---------------------------------------------------------------------------
// Launch
// ---------------------------------------------------------------------------
extern "C" void kernel_launch(void* const* d_in, const int* in_sizes, int n_in,
                              void* d_out, int out_size) {
    const float* X       = (const float*)d_in[0];
    const int*   row_ids = (const int*)d_in[1];
    const int*   col_ids = (const int*)d_in[2];
    const float* W1 = (const float*)d_in[3];
    const float* b1 = (const float*)d_in[4];
    const float* W2 = (const float*)d_in[5];
    const float* b2 = (const float*)d_in[6];
    const float* W3 = (const float*)d_in[7];
    const float* b3 = (const float*)d_in[8];
    float* out = (float*)d_out;

    dim3 grid(NCOLS / STRIP_COLS, NROWS / ROWS_PER_CTA);   // (16, 64)
    mar_reduce_kernel<<<grid, THREADS_RED>>>(X, row_ids, col_ids, out);

    mar_l1_kernel<<<16, 256>>>(W1);
    mar_l2_kernel<<<1, 128>>>(b1, W2, b2);
    mar_l3_kernel<<<8, 512>>>(W3, b3, out);
}

// round 6
// speedup vs baseline: 1.0599x; 1.0599x over previous
#include <cuda_runtime.h>
#include <math.h>

#define NROWS 8192
#define NCOLS 8192
#define RB 32
#define CB 32
#define HID 100
#define DIO (RB * CB)                  // 1024
#define ROWS_PER_CTA 128
#define THREADS_RED 128
#define STRIP_COLS (THREADS_RED * 4)   // 512 columns per CTA strip
#define ST_V4 (NCOLS / 4)              // float4 row stride
#define MAXRUNS 33
#define TAIL_CTAS 16

// Device-global scratch (no allocations allowed). g_blk/g_h1 are accumulators
// re-zeroed after consumption; g_count/g_flag are reset by the reduce kernel
// (stream-ordered before the tail kernel each replay). g_h2/g_rcum/g_ccum
// are fully overwritten each replay.
__device__ float g_blk[DIO];
__device__ float g_h1[HID];
__device__ float g_h2[HID];
__device__ int   g_rcum[RB + 1];
__device__ int   g_ccum[CB + 1];
__device__ unsigned int g_count;
__device__ int   g_flag;

__device__ __forceinline__ int lb_count_less(const int* __restrict__ a,
                                             int n, int key) {
    int lo = 0, hi = n;
    while (lo < hi) {
        int mid = (lo + hi) >> 1;
        if (__ldg(&a[mid]) < key) lo = mid + 1; else hi = mid;
    }
    return lo;
}

// ---------------------------------------------------------------------------
// Kernel 1: segmented block-sum reduce of X (HBM-bound, ~99.9% of bytes).
// Grid (16, 64) = 1024 CTAs x 128 thr. Run-based branch-free hot loop with
// 8 front-batched float4 streaming loads (MLP ~ 8 — measured optimum).
// CTA (0,0) additionally computes the cumsums and resets the tail's
// counter/flag for this replay.
// ---------------------------------------------------------------------------
__global__ __launch_bounds__(THREADS_RED)
void mar_reduce_kernel(const float* __restrict__ X,
                       const int* __restrict__ row_ids,
                       const int* __restrict__ col_ids,
                       float* __restrict__ out) {
    __shared__ float s_blk[DIO];
    __shared__ unsigned char s_rseg[ROWS_PER_CTA];
    __shared__ short s_run_start[MAXRUNS + 1];
    __shared__ unsigned char s_run_seg[MAXRUNS];
    __shared__ int s_nrun;

    const int tid = threadIdx.x;
    const int r0 = blockIdx.y * ROWS_PER_CTA;
    const int c0 = blockIdx.x * STRIP_COLS + tid * 4;

    for (int i = tid; i < DIO; i += THREADS_RED) s_blk[i] = 0.0f;
    if (tid < ROWS_PER_CTA)
        s_rseg[tid] = (unsigned char)row_ids[r0 + tid];

    const int cs0 = col_ids[c0 + 0];
    const int cs1 = col_ids[c0 + 1];
    const int cs2 = col_ids[c0 + 2];
    const int cs3 = col_ids[c0 + 3];
    __syncthreads();

    // Build run list (sorted ids -> typically 1-2 runs per 128-row chunk).
    if (tid == 0) {
        int n = 0, prev = -1;
        for (int r = 0; r < ROWS_PER_CTA; r++) {
            int s = s_rseg[r];
            if (s != prev) {
                s_run_start[n] = (short)r;
                s_run_seg[n] = (unsigned char)s;
                n++; prev = s;
            }
        }
        s_run_start[n] = ROWS_PER_CTA;
        s_nrun = n;
    }
    __syncthreads();

    const float4* __restrict__ p = (const float4*)(X + (size_t)r0 * NCOLS + c0);
    const int nrun = s_nrun;

    for (int run = 0; run < nrun; run++) {
        const int rs = s_run_start[run];
        const int re = s_run_start[run + 1];
        const int seg = s_run_seg[run];
        const float4* __restrict__ q = p + (size_t)rs * ST_V4;
        const int n = re - rs;

        float a0 = 0.f, a1 = 0.f, a2 = 0.f, a3 = 0.f;
        float b0 = 0.f, b1 = 0.f, b2 = 0.f, b3 = 0.f;
        int r = 0;
        // 8 independent streaming loads batched up front; two accum quads
        // (halved dependent-FADD chain, no extra registers).
        for (; r + 8 <= n; r += 8) {
            float4 v0 = __ldcs(&q[(size_t)(r + 0) * ST_V4]);
            float4 v1 = __ldcs(&q[(size_t)(r + 1) * ST_V4]);
            float4 v2 = __ldcs(&q[(size_t)(r + 2) * ST_V4]);
            float4 v3 = __ldcs(&q[(size_t)(r + 3) * ST_V4]);
            float4 v4 = __ldcs(&q[(size_t)(r + 4) * ST_V4]);
            float4 v5 = __ldcs(&q[(size_t)(r + 5) * ST_V4]);
            float4 v6 = __ldcs(&q[(size_t)(r + 6) * ST_V4]);
            float4 v7 = __ldcs(&q[(size_t)(r + 7) * ST_V4]);
            a0 += v0.x; a1 += v0.y; a2 += v0.z; a3 += v0.w;
            b0 += v1.x; b1 += v1.y; b2 += v1.z; b3 += v1.w;
            a0 += v2.x; a1 += v2.y; a2 += v2.z; a3 += v2.w;
            b0 += v3.x; b1 += v3.y; b2 += v3.z; b3 += v3.w;
            a0 += v4.x; a1 += v4.y; a2 += v4.z; a3 += v4.w;
            b0 += v5.x; b1 += v5.y; b2 += v5.z; b3 += v5.w;
            a0 += v6.x; a1 += v6.y; a2 += v6.z; a3 += v6.w;
            b0 += v7.x; b1 += v7.y; b2 += v7.z; b3 += v7.w;
        }
        for (; r < n; r++) {
            float4 v = __ldcs(&q[(size_t)r * ST_V4]);
            a0 += v.x; a1 += v.y; a2 += v.z; a3 += v.w;
        }
        const int base = seg * CB;
        atomicAdd(&s_blk[base + cs0], a0 + b0);
        atomicAdd(&s_blk[base + cs1], a1 + b1);
        atomicAdd(&s_blk[base + cs2], a2 + b2);
        atomicAdd(&s_blk[base + cs3], a3 + b3);
    }
    __syncthreads();

    for (int i = tid; i < DIO; i += THREADS_RED) {
        float v = s_blk[i];
        if (v != 0.0f) atomicAdd(&g_blk[i], v);
    }

    // Side task (one CTA): cumsums + reset tail sync state for this replay.
    if (blockIdx.x == 0 && blockIdx.y == 0) {
        if (tid <= RB) {
            int v = lb_count_less(row_ids, NROWS, tid);
            g_rcum[tid] = v;
            out[DIO + tid] = (float)v;
        } else if (tid < 2 * (RB + 1)) {
            int t = tid - (RB + 1);
            int v = lb_count_less(col_ids, NCOLS, t);
            g_ccum[t] = v;
            out[DIO + (RB + 1) + t] = (float)v;
        } else if (tid == 2 * (RB + 1)) {
            g_count = 0;
        } else if (tid == 2 * (RB + 1) + 1) {
            g_flag = 0;
        }
    }
}

// ---------------------------------------------------------------------------
// Kernel 2 (fused tail), grid TAIL_CTAS=16 x 256 threads:
//  Phase A: L1 partials. CTA c: block-means for input rows [c*64,(c+1)*64),
//           two thread-halves of 32 rows, atomicAdd into g_h1. Resets its
//           own g_blk slice (after reading).
//  Phase B: arrival counter; LAST CTA computes relu(h1+b1) @ W2 -> g_h2,
//           resets g_h1, publishes flag. Others spin (all 16 CTAs resident).
//  Phase C: L3 split-K: CTA c owns output cols [c*64,(c+1)*64), 4 K-parts
//           of 25 rows, shared combine + sigmoid -> out.
// ---------------------------------------------------------------------------
__global__ __launch_bounds__(256)
void mar_tail_kernel(const float* __restrict__ W1, const float* __restrict__ b1,
                     const float* __restrict__ W2, const float* __restrict__ b2,
                     const float* __restrict__ W3, const float* __restrict__ b3,
                     float* __restrict__ out) {
    __shared__ float s_x[64];
    __shared__ float s_h1[HID];
    __shared__ float s_h2[HID];
    __shared__ float s_part[3][64];
    __shared__ int s_last;

    const int tid = threadIdx.x;
    const int cta = blockIdx.x;
    const int i0 = cta * 64;

    // ---- Phase A: block means + L1 partials ----
    if (tid < 64) {
        int i = i0 + tid;
        int ri = i >> 5, ci = i & 31;
        float rc = (float)(g_rcum[ri + 1] - g_rcum[ri]);
        float cc = (float)(g_ccum[ci + 1] - g_ccum[ci]);
        s_x[tid] = g_blk[i] / fmaxf(rc * cc, 1.0f);
        g_blk[i] = 0.0f;                    // consumed -> clean for next replay
    }
    __syncthreads();

    {
        const int half = tid >> 7;          // 0 or 1: 32 input rows each
        const int k = tid & 127;
        if (k < HID) {
            float s = 0.0f;
            const float* __restrict__ w = W1 + (size_t)(i0 + half * 32) * HID + k;
            const float* __restrict__ xs = s_x + half * 32;
#pragma unroll 32
            for (int i = 0; i < 32; i++)
                s += xs[i] * __ldg(&w[(size_t)i * HID]);
            atomicAdd(&g_h1[k], s);
        }
    }
    __threadfence();                        // h1 partials visible before arrive
    __syncthreads();

    // ---- Phase B: last-CTA does L2 ----
    if (tid == 0) {
        unsigned int v = atomicAdd(&g_count, 1u);
        s_last = (v == TAIL_CTAS - 1) ? 1 : 0;
    }
    __syncthreads();

    if (s_last) {
        if (tid < HID) {
            s_h1[tid] = fmaxf(__ldcg(&g_h1[tid]) + b1[tid], 0.0f);
            g_h1[tid] = 0.0f;               // clean for next replay
        }
        __syncthreads();
        if (tid < HID) {
            float s = b2[tid];
            const float* __restrict__ w = W2 + tid;
#pragma unroll 20
            for (int i = 0; i < HID; i++)
                s += s_h1[i] * __ldg(&w[(size_t)i * HID]);
            g_h2[tid] = fmaxf(s, 0.0f);
        }
        __threadfence();
        __syncthreads();
        if (tid == 0) atomicExch(&g_flag, 1);
    }

    // All CTAs wait for h2 (all 16 CTAs are co-resident: grid 16 << 148 SMs).
    if (tid == 0) {
        while (atomicAdd(&g_flag, 0) == 0) { }
    }
    __syncthreads();
    __threadfence();

    // ---- Phase C: L3 split-K + sigmoid ----
    if (tid < HID) s_h2[tid] = __ldcg(&g_h2[tid]);
    __syncthreads();

    const int lane = tid & 63;
    const int part = tid >> 6;              // 0..3, 25 rows each
    const int j = cta * 64 + lane;
    const int ibeg = part * 25;

    float s = 0.0f;
    const float* __restrict__ w = W3 + (size_t)ibeg * DIO + j;
#pragma unroll 25
    for (int i = 0; i < 25; i++)
        s += s_h2[ibeg + i] * __ldg(&w[(size_t)i * DIO]);

    if (part) s_part[part - 1][lane] = s;
    __syncthreads();
    if (part == 0) {
        s += b3[j] + s_part[0][lane] + s_part[1][lane] + s_part[2][lane];
        out[j] = 1.0f / (1.0f + expf(-s));
    }
}

// ---------------------------------------------------------------------------
// Launch
// ---------------------------------------------------------------------------
extern "C" void kernel_launch(void* const* d_in, const int* in_sizes, int n_in,
                              void* d_out, int out_size) {
    const float* X       = (const float*)d_in[0];
    const int*   row_ids = (const int*)d_in[1];
    const int*   col_ids = (const int*)d_in[2];
    const float* W1 = (const float*)d_in[3];
    const float* b1 = (const float*)d_in[4];
    const float* W2 = (const float*)d_in[5];
    const float* b2 = (const float*)d_in[6];
    const float* W3 = (const float*)d_in[7];
    const float* b3 = (const float*)d_in[8];
    float* out = (float*)d_out;

    dim3 grid(NCOLS / STRIP_COLS, NROWS / ROWS_PER_CTA);   // (16, 64)
    mar_reduce_kernel<<<grid, THREADS_RED>>>(X, row_ids, col_ids, out);

    mar_tail_kernel<<<TAIL_CTAS, 256>>>(W1, b1, W2, b2, W3, b3, out);
}